// round 5
// baseline (speedup 1.0000x reference)
#include <cuda_runtime.h>
#include <cuda_bf16.h>

#define D_DIM   1024
#define DV      256            // float4 groups per row
#define L_COMP  16384
#define L_FULL  32768
#define NCHUNK  512
#define CL      32             // L_COMP / NCHUNK
#define EPSF    1e-4f

// Scratch (allocation-free: __device__ globals)
__device__ float  g_A[NCHUNK];              // per-chunk decay product (scalar, shared across channels)
__device__ float4 g_B[NCHUNK * DV];         // per-chunk local-scan final value, layout [chunk][channel/4]
__device__ float4 g_Z0[NCHUNK * DV];        // state entering each chunk (exclusive prefix)
__device__ int    g_pos[L_COMP + 1];        // pos[r] = full-seq index of r-th boundary; pos[L_COMP]=L_FULL

// ---------------------------------------------------------------------------
// k0: boundary positions via ballot/popc block scan over b (exactly L_COMP ones)
// ---------------------------------------------------------------------------
__global__ void k0_pos(const int* __restrict__ b) {
    __shared__ int wsum[32];
    int tid  = threadIdx.x;
    int lane = tid & 31;
    int wid  = tid >> 5;
    if (tid == 0) g_pos[L_COMP] = L_FULL;
    unsigned lemask = (2u << lane) - 1u;   // lanes <= me (lane=31 -> 0xFFFFFFFF)
    int carry = 0;
    for (int base = 0; base < L_FULL; base += 1024) {
        int v = b[base + tid];
        unsigned m = __ballot_sync(0xFFFFFFFFu, v != 0);
        int incl = __popc(m & lemask);
        if (lane == 0) wsum[wid] = __popc(m);
        __syncthreads();
        if (wid == 0) {
            int s = wsum[lane];
            #pragma unroll
            for (int o = 1; o < 32; o <<= 1) {
                int n = __shfl_up_sync(0xFFFFFFFFu, s, o);
                if (lane >= o) s += n;
            }
            wsum[lane] = s;
        }
        __syncthreads();
        int excl = wid ? wsum[wid - 1] : 0;
        if (v) g_pos[carry + excl + incl - 1] = base + tid;
        carry += wsum[31];
        __syncthreads();   // protect wsum reuse
    }
}

// ---------------------------------------------------------------------------
// k1: per-chunk aggregates. One block per chunk, 256 threads, float4/thread.
//     Batched 8-deep loads for MLP; recurrence chain is FMA-only.
// ---------------------------------------------------------------------------
__global__ __launch_bounds__(256) void k1_agg(const float4* __restrict__ x,
                                              const float* __restrict__ p) {
    int c = blockIdx.x, tid = threadIdx.x;
    int t0 = c * CL;
    __shared__ float s_p[CL], s_a[CL];
    if (tid < CL) {
        float pt = fminf(fmaxf(p[t0 + tid], EPSF), 1.0f - EPSF);
        s_p[tid] = pt;
        s_a[tid] = 1.0f - pt;
    }
    __syncthreads();

    const float4* xr = x + (size_t)t0 * DV + tid;
    float4 B = make_float4(0.f, 0.f, 0.f, 0.f);
    float  A = 1.0f;

    #pragma unroll
    for (int tb = 0; tb < CL; tb += 8) {
        float4 xv[8];
        #pragma unroll
        for (int k = 0; k < 8; k++) xv[k] = xr[(size_t)(tb + k) * DV];
        #pragma unroll
        for (int k = 0; k < 8; k++) {
            float a = s_a[tb + k], pt = s_p[tb + k];
            B.x = fmaf(a, B.x, pt * xv[k].x);
            B.y = fmaf(a, B.y, pt * xv[k].y);
            B.z = fmaf(a, B.z, pt * xv[k].z);
            B.w = fmaf(a, B.w, pt * xv[k].w);
            A *= a;
        }
    }
    g_B[c * DV + tid] = B;
    if (tid == 0) g_A[c] = A;
}

// ---------------------------------------------------------------------------
// k2: serial scan over NCHUNK chunk aggregates. 1 block, 256 threads
//     (one float4 channel-group each). Double-buffered 16-wide tiles hide L2.
// ---------------------------------------------------------------------------
#define K2T 16
__global__ __launch_bounds__(256) void k2_scan() {
    int v = threadIdx.x;
    __shared__ float sA[NCHUNK];
    for (int i = v; i < NCHUNK; i += 256) sA[i] = g_A[i];
    __syncthreads();

    float4 z = make_float4(0.f, 0.f, 0.f, 0.f);
    float4 buf[K2T], nbuf[K2T];
    #pragma unroll
    for (int k = 0; k < K2T; k++) buf[k] = g_B[k * DV + v];

    const int NT = NCHUNK / K2T;
    for (int tile = 0; tile < NT; tile++) {
        if (tile + 1 < NT) {
            int nb = (tile + 1) * K2T;
            #pragma unroll
            for (int k = 0; k < K2T; k++) nbuf[k] = g_B[(nb + k) * DV + v];
        }
        #pragma unroll
        for (int k = 0; k < K2T; k++) {
            int c = tile * K2T + k;
            g_Z0[c * DV + v] = z;                 // exclusive prefix (state entering chunk c)
            float a = sA[c];
            z.x = fmaf(a, z.x, buf[k].x);
            z.y = fmaf(a, z.y, buf[k].y);
            z.z = fmaf(a, z.z, buf[k].z);
            z.w = fmaf(a, z.w, buf[k].w);
        }
        #pragma unroll
        for (int k = 0; k < K2T; k++) buf[k] = nbuf[k];
    }
}

// ---------------------------------------------------------------------------
// k3: re-scan each chunk from Z0 and scatter z_t directly into the contiguous
//     out rows [pos[t], pos[t+1]) — fused gather, z never materialized.
// ---------------------------------------------------------------------------
__global__ __launch_bounds__(256) void k3_emit(const float4* __restrict__ x,
                                               const float* __restrict__ p,
                                               float4* __restrict__ out) {
    int c = blockIdx.x, tid = threadIdx.x;
    int t0 = c * CL;
    __shared__ float s_p[CL], s_a[CL];
    __shared__ int   s_pos[CL + 1];
    if (tid < CL) {
        float pt = fminf(fmaxf(p[t0 + tid], EPSF), 1.0f - EPSF);
        s_p[tid] = pt;
        s_a[tid] = 1.0f - pt;
    }
    if (tid < CL + 1) s_pos[tid] = g_pos[t0 + tid];
    __syncthreads();

    const float4* xr = x + (size_t)t0 * DV + tid;
    float4 z = g_Z0[c * DV + tid];

    #pragma unroll
    for (int tb = 0; tb < CL; tb += 8) {
        float4 xv[8];
        #pragma unroll
        for (int k = 0; k < 8; k++) xv[k] = xr[(size_t)(tb + k) * DV];
        #pragma unroll
        for (int k = 0; k < 8; k++) {
            int t = tb + k;
            float a = s_a[t], pt = s_p[t];
            z.x = fmaf(a, z.x, pt * xv[k].x);
            z.y = fmaf(a, z.y, pt * xv[k].y);
            z.z = fmaf(a, z.z, pt * xv[k].z);
            z.w = fmaf(a, z.w, pt * xv[k].w);
            int s = s_pos[t], e = s_pos[t + 1];
            for (int j = s; j < e; j++) out[(size_t)j * DV + tid] = z;
        }
    }
}

// ---------------------------------------------------------------------------
extern "C" void kernel_launch(void* const* d_in, const int* in_sizes, int n_in,
                              void* d_out, int out_size) {
    const float* x = (const float*)d_in[0];        // (1, 16384, 1024) fp32
    const float* p = (const float*)d_in[1];        // (16384,) fp32
    const int*   b = (const int*)d_in[2];          // (1, 32768) int32
    float* out = (float*)d_out;                    // (1, 32768, 1024) fp32

    k0_pos<<<1, 1024>>>(b);
    k1_agg<<<NCHUNK, 256>>>((const float4*)x, p);
    k2_scan<<<1, 256>>>();
    k3_emit<<<NCHUNK, 256>>>((const float4*)x, p, (float4*)out);
}

// round 7
// speedup vs baseline: 1.4694x; 1.4694x over previous
#include <cuda_runtime.h>
#include <cuda_bf16.h>

#define D_DIM   1024
#define DV      256            // float4 groups per row
#define L_COMP  16384
#define L_FULL  32768
#define NCHUNK  1024
#define CL      16             // L_COMP / NCHUNK
#define SC      32             // chunks per superchunk
#define NSUPER  32             // NCHUNK / SC
#define EPSF    1e-4f

// Scratch (allocation-free: __device__ globals)
__device__ float  g_A[NCHUNK];               // per-chunk decay product
__device__ float4 g_B[NCHUNK * DV];          // per-chunk local-scan final value
__device__ float4 g_Z0[NCHUNK * DV];         // state entering each chunk
__device__ float  g_As[NSUPER];              // superchunk decay product
__device__ float4 g_Bs[NSUPER * DV];         // superchunk aggregate B
__device__ float4 g_Z0s[NSUPER * DV];        // state entering each superchunk
__device__ int    g_pos[L_COMP + 1];         // boundary positions; pos[L_COMP]=L_FULL

// ---------------------------------------------------------------------------
// k0: boundary positions. All 32 loads per thread batched up-front (one DRAM
//     latency exposure instead of 32 serialized ones), then register scans.
// ---------------------------------------------------------------------------
__global__ void k0_pos(const int* __restrict__ b) {
    __shared__ int wsum[32];
    int tid  = threadIdx.x;
    int lane = tid & 31;
    int wid  = tid >> 5;
    if (tid == 0) g_pos[L_COMP] = L_FULL;

    int vals[32];
    #pragma unroll
    for (int k = 0; k < 32; k++) vals[k] = b[k * 1024 + tid];

    unsigned lemask = (2u << lane) - 1u;
    int carry = 0;
    #pragma unroll 1
    for (int k = 0; k < 32; k++) {
        unsigned m = __ballot_sync(0xFFFFFFFFu, vals[k] != 0);
        int incl = __popc(m & lemask);
        if (lane == 0) wsum[wid] = __popc(m);
        __syncthreads();
        if (wid == 0) {
            int s = wsum[lane];
            #pragma unroll
            for (int o = 1; o < 32; o <<= 1) {
                int n = __shfl_up_sync(0xFFFFFFFFu, s, o);
                if (lane >= o) s += n;
            }
            wsum[lane] = s;
        }
        __syncthreads();
        int excl = wid ? wsum[wid - 1] : 0;
        if (vals[k]) g_pos[carry + excl + incl - 1] = k * 1024 + tid;
        carry += wsum[31];
        __syncthreads();
    }
}

// ---------------------------------------------------------------------------
// k1: per-chunk aggregates. 1024 blocks x 256 threads, float4/thread,
//     8-deep batched loads.
// ---------------------------------------------------------------------------
__global__ __launch_bounds__(256) void k1_agg(const float4* __restrict__ x,
                                              const float* __restrict__ p) {
    int c = blockIdx.x, tid = threadIdx.x;
    int t0 = c * CL;
    __shared__ float s_p[CL], s_a[CL];
    if (tid < CL) {
        float pt = fminf(fmaxf(p[t0 + tid], EPSF), 1.0f - EPSF);
        s_p[tid] = pt;
        s_a[tid] = 1.0f - pt;
    }
    __syncthreads();

    const float4* xr = x + (size_t)t0 * DV + tid;
    float4 B = make_float4(0.f, 0.f, 0.f, 0.f);
    float  A = 1.0f;

    #pragma unroll
    for (int tb = 0; tb < CL; tb += 8) {
        float4 xv[8];
        #pragma unroll
        for (int k = 0; k < 8; k++) xv[k] = __ldcg(&xr[(size_t)(tb + k) * DV]);
        #pragma unroll
        for (int k = 0; k < 8; k++) {
            float a = s_a[tb + k], pt = s_p[tb + k];
            B.x = fmaf(a, B.x, pt * xv[k].x);
            B.y = fmaf(a, B.y, pt * xv[k].y);
            B.z = fmaf(a, B.z, pt * xv[k].z);
            B.w = fmaf(a, B.w, pt * xv[k].w);
            A *= a;
        }
    }
    g_B[c * DV + tid] = B;
    if (tid == 0) g_A[c] = A;
}

// ---------------------------------------------------------------------------
// k2a: superchunk aggregates. 32 blocks, each combines 32 chunk aggregates.
// ---------------------------------------------------------------------------
__global__ __launch_bounds__(256) void k2a_super() {
    int s = blockIdx.x, v = threadIdx.x;
    int c0 = s * SC;
    __shared__ float sA[SC];
    if (v < SC) sA[v] = g_A[c0 + v];
    __syncthreads();

    float4 B = make_float4(0.f, 0.f, 0.f, 0.f);
    float  A = 1.0f;
    #pragma unroll
    for (int kb = 0; kb < SC; kb += 8) {
        float4 Bc[8];
        #pragma unroll
        for (int k = 0; k < 8; k++) Bc[k] = g_B[(c0 + kb + k) * DV + v];
        #pragma unroll
        for (int k = 0; k < 8; k++) {
            float a = sA[kb + k];
            B.x = fmaf(a, B.x, Bc[k].x);
            B.y = fmaf(a, B.y, Bc[k].y);
            B.z = fmaf(a, B.z, Bc[k].z);
            B.w = fmaf(a, B.w, Bc[k].w);
            A *= a;
        }
    }
    g_Bs[s * DV + v] = B;
    if (v == 0) g_As[s] = A;
}

// ---------------------------------------------------------------------------
// k2b: serial scan over 32 superchunk aggregates. 1 block, tiny.
// ---------------------------------------------------------------------------
__global__ __launch_bounds__(256) void k2b_scan() {
    int v = threadIdx.x;
    __shared__ float sA[NSUPER];
    if (v < NSUPER) sA[v] = g_As[v];
    __syncthreads();

    float4 z = make_float4(0.f, 0.f, 0.f, 0.f);
    #pragma unroll
    for (int sb = 0; sb < NSUPER; sb += 8) {
        float4 Bs[8];
        #pragma unroll
        for (int k = 0; k < 8; k++) Bs[k] = g_Bs[(sb + k) * DV + v];
        #pragma unroll
        for (int k = 0; k < 8; k++) {
            g_Z0s[(sb + k) * DV + v] = z;
            float a = sA[sb + k];
            z.x = fmaf(a, z.x, Bs[k].x);
            z.y = fmaf(a, z.y, Bs[k].y);
            z.z = fmaf(a, z.z, Bs[k].z);
            z.w = fmaf(a, z.w, Bs[k].w);
        }
    }
}

// ---------------------------------------------------------------------------
// k2c: expand within superchunks -> per-chunk Z0. 32 blocks in parallel.
// ---------------------------------------------------------------------------
__global__ __launch_bounds__(256) void k2c_expand() {
    int s = blockIdx.x, v = threadIdx.x;
    int c0 = s * SC;
    __shared__ float sA[SC];
    if (v < SC) sA[v] = g_A[c0 + v];
    __syncthreads();

    float4 z = g_Z0s[s * DV + v];
    #pragma unroll
    for (int kb = 0; kb < SC; kb += 8) {
        float4 Bc[8];
        #pragma unroll
        for (int k = 0; k < 8; k++) Bc[k] = g_B[(c0 + kb + k) * DV + v];
        #pragma unroll
        for (int k = 0; k < 8; k++) {
            g_Z0[(c0 + kb + k) * DV + v] = z;
            float a = sA[kb + k];
            z.x = fmaf(a, z.x, Bc[k].x);
            z.y = fmaf(a, z.y, Bc[k].y);
            z.z = fmaf(a, z.z, Bc[k].z);
            z.w = fmaf(a, z.w, Bc[k].w);
        }
    }
}

// ---------------------------------------------------------------------------
// k3: re-scan each chunk from Z0, scatter z_t directly into contiguous out
//     rows [pos[t], pos[t+1]). Streaming stores keep x L2-resident.
// ---------------------------------------------------------------------------
__global__ __launch_bounds__(256) void k3_emit(const float4* __restrict__ x,
                                               const float* __restrict__ p,
                                               float4* __restrict__ out) {
    int c = blockIdx.x, tid = threadIdx.x;
    int t0 = c * CL;
    __shared__ float s_p[CL], s_a[CL];
    __shared__ int   s_pos[CL + 1];
    if (tid < CL) {
        float pt = fminf(fmaxf(p[t0 + tid], EPSF), 1.0f - EPSF);
        s_p[tid] = pt;
        s_a[tid] = 1.0f - pt;
    }
    if (tid < CL + 1) s_pos[tid] = g_pos[t0 + tid];
    __syncthreads();

    const float4* xr = x + (size_t)t0 * DV + tid;
    float4 z = g_Z0[c * DV + tid];

    #pragma unroll
    for (int tb = 0; tb < CL; tb += 8) {
        float4 xv[8];
        #pragma unroll
        for (int k = 0; k < 8; k++) xv[k] = __ldcg(&xr[(size_t)(tb + k) * DV]);
        #pragma unroll
        for (int k = 0; k < 8; k++) {
            int t = tb + k;
            float a = s_a[t], pt = s_p[t];
            z.x = fmaf(a, z.x, pt * xv[k].x);
            z.y = fmaf(a, z.y, pt * xv[k].y);
            z.z = fmaf(a, z.z, pt * xv[k].z);
            z.w = fmaf(a, z.w, pt * xv[k].w);
            int s = s_pos[t], e = s_pos[t + 1];
            for (int j = s; j < e; j++) __stcs(&out[(size_t)j * DV + tid], z);
        }
    }
}

// ---------------------------------------------------------------------------
extern "C" void kernel_launch(void* const* d_in, const int* in_sizes, int n_in,
                              void* d_out, int out_size) {
    const float* x = (const float*)d_in[0];        // (1, 16384, 1024) fp32
    const float* p = (const float*)d_in[1];        // (16384,) fp32
    const int*   b = (const int*)d_in[2];          // (1, 32768) int32
    float* out = (float*)d_out;                    // (1, 32768, 1024) fp32

    k0_pos<<<1, 1024>>>(b);
    k1_agg<<<NCHUNK, 256>>>((const float4*)x, p);
    k2a_super<<<NSUPER, 256>>>();
    k2b_scan<<<1, 256>>>();
    k2c_expand<<<NSUPER, 256>>>();
    k3_emit<<<NCHUNK, 256>>>((const float4*)x, p, (float4*)out);
}

// round 8
// speedup vs baseline: 1.4932x; 1.0162x over previous
#include <cuda_runtime.h>
#include <cuda_bf16.h>

#define D_DIM   1024
#define DV      256            // float4 groups per row
#define L_COMP  16384
#define L_FULL  32768
#define NCHUNK  512
#define CL      32             // L_COMP / NCHUNK
#define EPSF    1e-4f

// Scratch (allocation-free: __device__ globals)
__device__ float  g_aggA[NCHUNK];            // per-chunk decay product
__device__ float4 g_aggB[NCHUNK * DV];       // per-chunk local aggregate B
__device__ float4 g_pref[NCHUNK * DV];       // inclusive prefix through chunk c
__device__ int    g_flag[NCHUNK];            // 0=none, 1=aggregate ready, 2=prefix ready
__device__ int    g_pos[L_COMP + 1];         // boundary positions; pos[L_COMP]=L_FULL

// ---------------------------------------------------------------------------
// k0: clear lookback flags (graph replays!) + boundary positions via
//     batched loads and ballot/popc block scan.
// ---------------------------------------------------------------------------
__global__ void k0_pos(const int* __restrict__ b) {
    __shared__ int wsum[32];
    int tid  = threadIdx.x;
    int lane = tid & 31;
    int wid  = tid >> 5;

    if (tid < NCHUNK) g_flag[tid] = 0;       // reset decoupled-lookback flags
    if (tid == 0) g_pos[L_COMP] = L_FULL;

    int vals[32];
    #pragma unroll
    for (int k = 0; k < 32; k++) vals[k] = b[k * 1024 + tid];

    unsigned lemask = (2u << lane) - 1u;
    int carry = 0;
    #pragma unroll 1
    for (int k = 0; k < 32; k++) {
        unsigned m = __ballot_sync(0xFFFFFFFFu, vals[k] != 0);
        int incl = __popc(m & lemask);
        if (lane == 0) wsum[wid] = __popc(m);
        __syncthreads();
        if (wid == 0) {
            int s = wsum[lane];
            #pragma unroll
            for (int o = 1; o < 32; o <<= 1) {
                int n = __shfl_up_sync(0xFFFFFFFFu, s, o);
                if (lane >= o) s += n;
            }
            wsum[lane] = s;
        }
        __syncthreads();
        int excl = wid ? wsum[wid - 1] : 0;
        if (vals[k]) g_pos[carry + excl + incl - 1] = k * 1024 + tid;
        carry += wsum[31];
        __syncthreads();
    }
    __threadfence();                         // flags + pos visible before k_scan
}

// ---------------------------------------------------------------------------
// k_scan: single-pass fused scan with decoupled lookback + fused gather.
//   Pass A : chunk aggregate (A scalar, B float4/thread), publish (fence+flag).
//   Lookback: combine predecessor aggregates until a prefix flag; get Z0.
//   Publish : inclusive prefix for successors.
//   Pass B : re-scan chunk from Z0 (x re-read is L2-hot), scatter z_t to the
//            contiguous out rows [pos[t], pos[t+1]) with streaming stores.
// ---------------------------------------------------------------------------
__global__ __launch_bounds__(256) void k_scan(const float4* __restrict__ x,
                                              const float* __restrict__ p,
                                              float4* __restrict__ out) {
    int c   = blockIdx.x;
    int tid = threadIdx.x;
    int t0  = c * CL;

    __shared__ float s_p[CL], s_a[CL];
    __shared__ int   s_pos[CL + 1];
    __shared__ int   s_flag;

    if (tid < CL) {
        float pt = fminf(fmaxf(p[t0 + tid], EPSF), 1.0f - EPSF);
        s_p[tid] = pt;
        s_a[tid] = 1.0f - pt;
    }
    if (tid < CL + 1) s_pos[tid] = g_pos[t0 + tid];
    __syncthreads();

    const float4* xr = x + (size_t)t0 * DV + tid;

    // ---- Pass A: local chunk aggregate ----
    float4 B = make_float4(0.f, 0.f, 0.f, 0.f);
    float  A = 1.0f;
    #pragma unroll
    for (int tb = 0; tb < CL; tb += 8) {
        float4 xv[8];
        #pragma unroll
        for (int k = 0; k < 8; k++) xv[k] = __ldcg(&xr[(size_t)(tb + k) * DV]);
        #pragma unroll
        for (int k = 0; k < 8; k++) {
            float a = s_a[tb + k], pt = s_p[tb + k];
            B.x = fmaf(a, B.x, pt * xv[k].x);
            B.y = fmaf(a, B.y, pt * xv[k].y);
            B.z = fmaf(a, B.z, pt * xv[k].z);
            B.w = fmaf(a, B.w, pt * xv[k].w);
            A *= a;
        }
    }

    float4 z;   // state entering this chunk (Z0)

    if (c == 0) {
        z = make_float4(0.f, 0.f, 0.f, 0.f);
        g_pref[tid] = B;                     // inclusive prefix of chunk 0 is B
        __threadfence();
        __syncthreads();
        if (tid == 0) atomicExch(&g_flag[0], 2);
    } else {
        // publish aggregate
        g_aggB[c * DV + tid] = B;
        if (tid == 0) g_aggA[c] = A;
        __threadfence();
        __syncthreads();
        if (tid == 0) atomicExch(&g_flag[c], 1);

        // ---- decoupled lookback ----
        float  As = 1.0f;
        float4 Bs = make_float4(0.f, 0.f, 0.f, 0.f);
        int j = c - 1;
        while (true) {
            if (tid == 0) {
                int f;
                do {
                    f = *((volatile int*)(g_flag + j));
                    if (f == 0) __nanosleep(40);
                } while (f == 0);
                s_flag = f;
            }
            __syncthreads();
            int f = s_flag;
            if (f == 2) {
                float4 Pj = __ldcg(&g_pref[j * DV + tid]);
                z.x = fmaf(As, Pj.x, Bs.x);
                z.y = fmaf(As, Pj.y, Bs.y);
                z.z = fmaf(As, Pj.z, Bs.z);
                z.w = fmaf(As, Pj.w, Bs.w);
                break;
            }
            float  Aj = __ldcg(&g_aggA[j]);
            float4 Bj = __ldcg(&g_aggB[j * DV + tid]);
            Bs.x = fmaf(As, Bj.x, Bs.x);
            Bs.y = fmaf(As, Bj.y, Bs.y);
            Bs.z = fmaf(As, Bj.z, Bs.z);
            Bs.w = fmaf(As, Bj.w, Bs.w);
            As *= Aj;
            j--;
            if (j < 0) { z = Bs; break; }    // unreachable (flag[0]→2), but safe
            __syncthreads();                 // protect s_flag reuse
        }

        // publish inclusive prefix: P_c = A*Z0 + B
        float4 P;
        P.x = fmaf(A, z.x, B.x);
        P.y = fmaf(A, z.y, B.y);
        P.z = fmaf(A, z.z, B.z);
        P.w = fmaf(A, z.w, B.w);
        g_pref[c * DV + tid] = P;
        __threadfence();
        __syncthreads();
        if (tid == 0) atomicExch(&g_flag[c], 2);
    }

    // ---- Pass B: emit. x re-read is L2-hot; fused gather via pos ranges ----
    #pragma unroll
    for (int tb = 0; tb < CL; tb += 8) {
        float4 xv[8];
        #pragma unroll
        for (int k = 0; k < 8; k++) xv[k] = __ldcg(&xr[(size_t)(tb + k) * DV]);
        #pragma unroll
        for (int k = 0; k < 8; k++) {
            int t = tb + k;
            float a = s_a[t], pt = s_p[t];
            z.x = fmaf(a, z.x, pt * xv[k].x);
            z.y = fmaf(a, z.y, pt * xv[k].y);
            z.z = fmaf(a, z.z, pt * xv[k].z);
            z.w = fmaf(a, z.w, pt * xv[k].w);
            int s = s_pos[t], e = s_pos[t + 1];
            for (int jj = s; jj < e; jj++)
                __stcs(&out[(size_t)jj * DV + tid], z);
        }
    }
}

// ---------------------------------------------------------------------------
extern "C" void kernel_launch(void* const* d_in, const int* in_sizes, int n_in,
                              void* d_out, int out_size) {
    const float* x = (const float*)d_in[0];        // (1, 16384, 1024) fp32
    const float* p = (const float*)d_in[1];        // (16384,) fp32
    const int*   b = (const int*)d_in[2];          // (1, 32768) int32
    float* out = (float*)d_out;                    // (1, 32768, 1024) fp32

    k0_pos<<<1, 1024>>>(b);
    k_scan<<<NCHUNK, 256>>>((const float4*)x, p, (float4*)out);
}